// round 4
// baseline (speedup 1.0000x reference)
#include <cuda_runtime.h>

// Problem constants (fixed shapes from the reference).
#define BSZ   16384
#define FCAST 365
#define JW    10
#define WU    30
#define TILE_D 40          // days per smem tile (multiple of JW)
#define BLOCK  128
#define SPAD   (TILE_D + 1) // 41: stride pad; 41 mod 32 = 9, coprime -> conflict-free

typedef unsigned long long u64;

// ---- packed f32x2 helpers (sm_100+ packed fp32 pipe; lo = v0, hi = v1) ----
__device__ __forceinline__ u64 ffma2(u64 a, u64 b, u64 c) {
    u64 d;
    asm("fma.rn.f32x2 %0, %1, %2, %3;" : "=l"(d) : "l"(a), "l"(b), "l"(c));
    return d;
}
__device__ __forceinline__ u64 fmul2(u64 a, u64 b) {
    u64 d;
    asm("mul.rn.f32x2 %0, %1, %2;" : "=l"(d) : "l"(a), "l"(b));
    return d;
}
__device__ __forceinline__ u64 pack2(float lo, float hi) {
    u64 r;
    asm("mov.b64 %0, {%1, %2};" : "=l"(r) : "f"(lo), "f"(hi));
    return r;
}
__device__ __forceinline__ void unpack2(u64 v, float& lo, float& hi) {
    asm("mov.b64 {%0, %1}, %2;" : "=f"(lo), "=f"(hi) : "l"(v));
}

__global__ __launch_bounds__(BLOCK, 1)
void covid_scan_kernel(const float* __restrict__ r_t,      // (B, 365)
                       const float* __restrict__ wA,       // (2, B, 30)
                       const float* __restrict__ wM,       // (2, B, 30)
                       const float* __restrict__ wE,       // (2, B, 30)
                       const float* __restrict__ eps,      // (1,)
                       const float* __restrict__ delta,    // (2,)
                       const float* __restrict__ rhoM,     // (2,)
                       const float* __restrict__ rhoX,     // (2,)
                       const float* __restrict__ rhoG,     // (2,)
                       const float* __restrict__ piM,      // (2, 10)
                       const float* __restrict__ piX,      // (2, 10)
                       const float* __restrict__ piG,      // (2, 10)
                       float* __restrict__ out)            // (B, 365)
{
    __shared__ float sRt [BLOCK * SPAD];   // staged rt^(1/T)
    __shared__ float sOut[BLOCK * SPAD];   // staged g output

    const int tid = threadIdx.x;
    const int b0  = blockIdx.x * BLOCK;
    const int b   = b0 + tid;

    const float inv_T = (float)(1.0 / 5.8);
    const float eps_s = eps[0];
    const u64 delta2 = pack2(delta[0], delta[1]);

    // Per-thread state, all packed (v0 in lo, v1 in hi).
    // Ring convention: slot p holds the value for day d with d % 10 == p
    // (negative days = warmup). Before day 0, slot p = warmup[..., 20 + p].
    u64 aR[JW], mR[JW], eR[JW];
    u64 wpiM[JW], wpiX[JW], wpiG[JW];

    // Fold rho into pi once (saves 3 packed muls/day).
    {
        const float rM0 = rhoM[0], rM1 = rhoM[1];
        const float rX0 = rhoX[0], rX1 = rhoX[1];
        const float rG0 = rhoG[0], rG1 = rhoG[1];
#pragma unroll
        for (int j = 0; j < JW; ++j) {
            wpiM[j] = pack2(rM0 * piM[j], rM1 * piM[JW + j]);
            wpiX[j] = pack2(rX0 * piX[j], rX1 * piX[JW + j]);
            wpiG[j] = pack2(rG0 * piG[j], rG1 * piG[JW + j]);
        }
    }

    // Warmup init: buf[j] = warmup[..., 29-j] (day -(j+1)); slot p <=> warmup[20+p].
    {
        const size_t off0 = (size_t)b * WU + 20;
        const size_t off1 = (size_t)BSZ * WU + off0;
#pragma unroll
        for (int p = 0; p < JW; ++p) {
            aR[p] = pack2(wA[off0 + p], wA[off1 + p]);
            mR[p] = pack2(wM[off0 + p], wM[off1 + p]);
            eR[p] = pack2(wE[off0 + p], wE[off1 + p]);
        }
    }

    const int ntiles = (FCAST + TILE_D - 1) / TILE_D;   // 10
    for (int tile = 0; tile < ntiles; ++tile) {
        const int t0 = tile * TILE_D;

        // ---- Stage rt tile, coalesced, applying pow off the serial path ----
        for (int i = tid; i < BLOCK * TILE_D; i += BLOCK) {
            const int r = i / TILE_D;
            const int d = i - r * TILE_D;
            const int t = t0 + d;
            float v = 1.0f;
            if (t < FCAST) v = r_t[(size_t)(b0 + r) * FCAST + t];
            sRt[r * SPAD + d] = exp2f(__log2f(v) * inv_T);
        }
        __syncthreads();

        // ---- Serial scan: unroll by JW so the ring rotates to identity ----
        // (t0 and blk*JW are multiples of 10, so t % 10 == s at compile time)
        for (int blk = 0; blk < TILE_D / JW; ++blk) {
#pragma unroll
            for (int s = 0; s < JW; ++s) {
                const int d = blk * JW + s;
                const int t = t0 + d;
                if (t < FCAST) {
                    u64 dM = 0ull, dX = 0ull, dG = 0ull;
                    // window j uses day t-1-j -> slot (s + 9 - j) % 10 (compile-time)
#pragma unroll
                    for (int j = 0; j < JW; ++j) {
                        const int p = (s + 9 - j) % JW;
                        dM = ffma2(aR[p], wpiM[j], dM);
                        dX = ffma2(mR[p], wpiX[j], dX);
                        dG = ffma2(eR[p], wpiG[j], dG);
                    }
                    // a_new from yesterday's asymp (slot (s+9)%10)
                    float a0lo, a0hi;
                    unpack2(aR[(s + 9) % JW], a0lo, a0hi);
                    const float comb = fmaf(eps_s, a0hi, a0lo);
                    const float sa   = comb * sRt[tid * SPAD + d];
                    aR[s] = fmul2(pack2(sa, sa), delta2);   // comb*delta_v*pow
                    mR[s] = dM;                              // m_new (rho folded)
                    eR[s] = dX;                              // x_new -> extreme buf
                    float glo, ghi;
                    unpack2(dG, glo, ghi);
                    sOut[tid * SPAD + d] = glo + ghi;        // g0 + g1
                }
            }
        }
        __syncthreads();

        // ---- Flush output tile, coalesced ----
        for (int i = tid; i < BLOCK * TILE_D; i += BLOCK) {
            const int r = i / TILE_D;
            const int d = i - r * TILE_D;
            const int t = t0 + d;
            if (t < FCAST) out[(size_t)(b0 + r) * FCAST + t] = sOut[r * SPAD + d];
        }
        __syncthreads();
    }
}

extern "C" void kernel_launch(void* const* d_in, const int* in_sizes, int n_in,
                              void* d_out, int out_size)
{
    const float* r_t   = (const float*)d_in[0];   // (B, 365)
    const float* wA    = (const float*)d_in[1];   // (2, B, 30)
    const float* wM    = (const float*)d_in[2];   // (2, B, 30)
    const float* wE    = (const float*)d_in[3];   // (2, B, 30)
    const float* eps   = (const float*)d_in[4];   // (1,)
    const float* delta = (const float*)d_in[5];   // (2,)
    const float* rhoM  = (const float*)d_in[6];   // (2,)
    const float* rhoX  = (const float*)d_in[7];   // (2,)
    const float* rhoG  = (const float*)d_in[8];   // (2,)
    const float* piM   = (const float*)d_in[9];   // (2, 10)
    const float* piX   = (const float*)d_in[10];  // (2, 10)
    const float* piG   = (const float*)d_in[11];  // (2, 10)
    float* out = (float*)d_out;

    covid_scan_kernel<<<BSZ / BLOCK, BLOCK>>>(
        r_t, wA, wM, wE, eps, delta, rhoM, rhoX, rhoG, piM, piX, piG, out);
}

// round 5
// speedup vs baseline: 1.0004x; 1.0004x over previous
#include <cuda_runtime.h>

// Problem constants (fixed shapes from the reference).
#define BSZ   16384
#define FCAST 365
#define JW    10
#define WU    30
#define TILE_D 40          // days per smem tile (multiple of JW)
#define BLOCK  128
#define SPAD   (TILE_D + 1) // 41: stride pad; 41 mod 32 = 9, coprime -> conflict-free

typedef unsigned long long u64;

// ---- packed f32x2 helpers (sm_100+ packed fp32 pipe; lo = v0, hi = v1) ----
__device__ __forceinline__ u64 ffma2(u64 a, u64 b, u64 c) {
    u64 d;
    asm("fma.rn.f32x2 %0, %1, %2, %3;" : "=l"(d) : "l"(a), "l"(b), "l"(c));
    return d;
}
__device__ __forceinline__ u64 fmul2(u64 a, u64 b) {
    u64 d;
    asm("mul.rn.f32x2 %0, %1, %2;" : "=l"(d) : "l"(a), "l"(b));
    return d;
}
__device__ __forceinline__ u64 pack2(float lo, float hi) {
    u64 r;
    asm("mov.b64 %0, {%1, %2};" : "=l"(r) : "f"(lo), "f"(hi));
    return r;
}
__device__ __forceinline__ void unpack2(u64 v, float& lo, float& hi) {
    asm("mov.b64 {%0, %1}, %2;" : "=f"(lo), "=f"(hi) : "l"(v));
}

__global__ __launch_bounds__(BLOCK, 1)
void covid_scan_kernel(const float* __restrict__ r_t,      // (B, 365)
                       const float* __restrict__ wA,       // (2, B, 30)
                       const float* __restrict__ wM,       // (2, B, 30)
                       const float* __restrict__ wE,       // (2, B, 30)
                       const float* __restrict__ eps,      // (1,)
                       const float* __restrict__ delta,    // (2,)
                       const float* __restrict__ rhoM,     // (2,)
                       const float* __restrict__ rhoX,     // (2,)
                       const float* __restrict__ rhoG,     // (2,)
                       const float* __restrict__ piM,      // (2, 10)
                       const float* __restrict__ piX,      // (2, 10)
                       const float* __restrict__ piG,      // (2, 10)
                       float* __restrict__ out)            // (B, 365)
{
    __shared__ float sRt [BLOCK * SPAD];   // staged rt^(1/T)
    __shared__ float sOut[BLOCK * SPAD];   // staged g output

    const int tid = threadIdx.x;
    const int b0  = blockIdx.x * BLOCK;
    const int b   = b0 + tid;

    const float inv_T = (float)(1.0 / 5.8);
    const float eps_s = eps[0];
    const u64 delta2 = pack2(delta[0], delta[1]);

    // Per-thread state, all packed (v0 in lo, v1 in hi).
    // Ring convention: slot p holds the value for day d with d % 10 == p
    // (negative days = warmup). Before day 0, slot p = warmup[..., 20 + p].
    u64 aR[JW], mR[JW], eR[JW];
    u64 wpiM[JW], wpiX[JW], wpiG[JW];

    // Fold rho into pi once (saves 3 packed muls/day).
    {
        const float rM0 = rhoM[0], rM1 = rhoM[1];
        const float rX0 = rhoX[0], rX1 = rhoX[1];
        const float rG0 = rhoG[0], rG1 = rhoG[1];
#pragma unroll
        for (int j = 0; j < JW; ++j) {
            wpiM[j] = pack2(rM0 * piM[j], rM1 * piM[JW + j]);
            wpiX[j] = pack2(rX0 * piX[j], rX1 * piX[JW + j]);
            wpiG[j] = pack2(rG0 * piG[j], rG1 * piG[JW + j]);
        }
    }

    // Warmup init: buf[j] = warmup[..., 29-j] (day -(j+1)); slot p <=> warmup[20+p].
    {
        const size_t off0 = (size_t)b * WU + 20;
        const size_t off1 = (size_t)BSZ * WU + off0;
#pragma unroll
        for (int p = 0; p < JW; ++p) {
            aR[p] = pack2(wA[off0 + p], wA[off1 + p]);
            mR[p] = pack2(wM[off0 + p], wM[off1 + p]);
            eR[p] = pack2(wE[off0 + p], wE[off1 + p]);
        }
    }

    const int ntiles = (FCAST + TILE_D - 1) / TILE_D;   // 10
    for (int tile = 0; tile < ntiles; ++tile) {
        const int t0 = tile * TILE_D;

        // ---- Stage rt tile, coalesced, applying pow off the serial path ----
        for (int i = tid; i < BLOCK * TILE_D; i += BLOCK) {
            const int r = i / TILE_D;
            const int d = i - r * TILE_D;
            const int t = t0 + d;
            float v = 1.0f;
            if (t < FCAST) v = r_t[(size_t)(b0 + r) * FCAST + t];
            sRt[r * SPAD + d] = exp2f(__log2f(v) * inv_T);
        }
        __syncthreads();

        // ---- Serial scan: unroll by JW so the ring rotates to identity ----
        // (t0 and blk*JW are multiples of 10, so t % 10 == s at compile time)
        for (int blk = 0; blk < TILE_D / JW; ++blk) {
#pragma unroll
            for (int s = 0; s < JW; ++s) {
                const int d = blk * JW + s;
                const int t = t0 + d;
                if (t < FCAST) {
                    u64 dM = 0ull, dX = 0ull, dG = 0ull;
                    // window j uses day t-1-j -> slot (s + 9 - j) % 10 (compile-time)
#pragma unroll
                    for (int j = 0; j < JW; ++j) {
                        const int p = (s + 9 - j) % JW;
                        dM = ffma2(aR[p], wpiM[j], dM);
                        dX = ffma2(mR[p], wpiX[j], dX);
                        dG = ffma2(eR[p], wpiG[j], dG);
                    }
                    // a_new from yesterday's asymp (slot (s+9)%10)
                    float a0lo, a0hi;
                    unpack2(aR[(s + 9) % JW], a0lo, a0hi);
                    const float comb = fmaf(eps_s, a0hi, a0lo);
                    const float sa   = comb * sRt[tid * SPAD + d];
                    aR[s] = fmul2(pack2(sa, sa), delta2);   // comb*delta_v*pow
                    mR[s] = dM;                              // m_new (rho folded)
                    eR[s] = dX;                              // x_new -> extreme buf
                    float glo, ghi;
                    unpack2(dG, glo, ghi);
                    sOut[tid * SPAD + d] = glo + ghi;        // g0 + g1
                }
            }
        }
        __syncthreads();

        // ---- Flush output tile, coalesced ----
        for (int i = tid; i < BLOCK * TILE_D; i += BLOCK) {
            const int r = i / TILE_D;
            const int d = i - r * TILE_D;
            const int t = t0 + d;
            if (t < FCAST) out[(size_t)(b0 + r) * FCAST + t] = sOut[r * SPAD + d];
        }
        __syncthreads();
    }
}

extern "C" void kernel_launch(void* const* d_in, const int* in_sizes, int n_in,
                              void* d_out, int out_size)
{
    const float* r_t   = (const float*)d_in[0];   // (B, 365)
    const float* wA    = (const float*)d_in[1];   // (2, B, 30)
    const float* wM    = (const float*)d_in[2];   // (2, B, 30)
    const float* wE    = (const float*)d_in[3];   // (2, B, 30)
    const float* eps   = (const float*)d_in[4];   // (1,)
    const float* delta = (const float*)d_in[5];   // (2,)
    const float* rhoM  = (const float*)d_in[6];   // (2,)
    const float* rhoX  = (const float*)d_in[7];   // (2,)
    const float* rhoG  = (const float*)d_in[8];   // (2,)
    const float* piM   = (const float*)d_in[9];   // (2, 10)
    const float* piX   = (const float*)d_in[10];  // (2, 10)
    const float* piG   = (const float*)d_in[11];  // (2, 10)
    float* out = (float*)d_out;

    covid_scan_kernel<<<BSZ / BLOCK, BLOCK>>>(
        r_t, wA, wM, wE, eps, delta, rhoM, rhoX, rhoG, piM, piX, piG, out);
}